// round 16
// baseline (speedup 1.0000x reference)
#include <cuda_runtime.h>
#include <cuda_fp16.h>
#include <cstdint>

// ---------------- Problem constants ----------------
#define HB   1024          // NUM_BASIC (K)
#define HM   8192          // NUM_MIXED (GEMM M)
#define RR   735           // T*7*7 rows of X (GEMM N, logical)
#define RPAD 768           // padded N
#define NN   57            // output matrix dim
#define OUTN (NN*NN)       // 3249

// ---------------- Scratch (device globals; no allocs allowed) ----------------
__device__ __half g_Xh[RPAD * HB];             // 1.5 MB : X in fp16, rows 735..767 zero
__device__ __half g_Wh[HM * HB];               // 16.7 MB: W in fp16 (RN)
__device__ float  g_Y [(size_t)HM * RPAD];     // 25 MB  : relu(X@W^T + b), [hm][r]

// ---------------- helpers ----------------
__device__ __forceinline__ void cp16(uint32_t s, const void* g) {
    asm volatile("cp.async.cg.shared.global [%0], [%1], 16;" :: "r"(s), "l"(g));
}
__device__ __forceinline__ void mma_f16(float* c, const uint32_t* a, const uint32_t* b) {
    asm volatile(
        "mma.sync.aligned.m16n8k16.row.col.f32.f16.f16.f32 "
        "{%0,%1,%2,%3}, {%4,%5,%6,%7}, {%8,%9}, {%0,%1,%2,%3};"
        : "+f"(c[0]), "+f"(c[1]), "+f"(c[2]), "+f"(c[3])
        : "r"(a[0]), "r"(a[1]), "r"(a[2]), "r"(a[3]), "r"(b[0]), "r"(b[1]));
}
__device__ __forceinline__ void ldsm4(uint32_t* r, uint32_t addr) {
    asm volatile("ldmatrix.sync.aligned.m8n8.x4.shared.b16 {%0,%1,%2,%3}, [%4];"
        : "=r"(r[0]), "=r"(r[1]), "=r"(r[2]), "=r"(r[3]) : "r"(addr));
}

// ---------------- Kernel 1: fused prep (convert W + build X) ----------------
__global__ __launch_bounds__(512) void prep_kernel(const float* __restrict__ mat,
                                                   const float* __restrict__ te,
                                                   const float4* __restrict__ W) {
    const int b = blockIdx.x;
    if (b < 100) {
        const int p = b >> 1;
        const int h = (b & 1) * 512 + threadIdx.x;
        if (p == 49) {  // zero padding rows 735..767
            #pragma unroll
            for (int row = RR; row < RPAD; row++) g_Xh[row * HB + h] = __ushort_as_half(0);
            return;
        }
        const int m = p / 7, n = p % 7;
        const float mv = fmaxf(mat[h * 49 + n * 7 + m], 0.f);
        const int rb = m * 7 + n;
        #pragma unroll
        for (int t = 0; t < 15; t++) {
            float s = 1.f + 1.f / (1.f + __expf(-te[h * 15 + t]));
            g_Xh[(t * 49 + rb) * HB + h] = __float2half_rn(s * mv);
        }
    } else {
        const int i = (b - 100) * 512 + threadIdx.x;   // 0 .. HM*HB/8-1
        float4 v0 = W[i * 2];
        float4 v1 = W[i * 2 + 1];
        __half2 h[4];
        h[0] = __floats2half2_rn(v0.x, v0.y);
        h[1] = __floats2half2_rn(v0.z, v0.w);
        h[2] = __floats2half2_rn(v1.x, v1.y);
        h[3] = __floats2half2_rn(v1.z, v1.w);
        *reinterpret_cast<uint4*>(&g_Wh[(size_t)i * 8]) = *reinterpret_cast<uint4*>(h);
    }
}

// ---------------- Kernel 2: fp16 mma.sync GEMM, 128x96 CTA tile, 32x48 warptile ----------------
// (R13 proven config: KTH=32, 3-stage, wait_group 1)
#define NT   96            // N tile
#define KTH  32            // K halfs per smem stage
#define KSH  40            // smem row stride in halfs: 80B rows -> conflict-free LDSM/STS
#define KTILES (HB / KTH)  // 32
#define NSTAGE 3
#define A_H (128 * KSH)                     // A halfs per stage (5120)
#define B_H (NT * KSH)                      // B halfs per stage (3840)
#define STAGE_T (A_H + B_H)                 // 8960 halfs per stage
#define GEMM_DYN (NSTAGE * STAGE_T * 2)     // 53760 bytes
#define CHUNKS ((128 + NT) * 4)             // 16B chunks per stage = 896

extern __shared__ __half g_sm[];

__global__ __launch_bounds__(256, 2) void gemm_kernel(const float* __restrict__ bias) {
    const int tid  = threadIdx.x;
    const int lane = tid & 31, warp = tid >> 5;
    const int g  = lane >> 2, t4 = lane & 3;
    const int mb = (warp >> 1) * 32;   // warp grid 4(M) x 2(N)
    const int nb = (warp & 1) * 48;
    const int m0 = blockIdx.y * 128;
    const int n0 = blockIdx.x * NT;

    const uint32_t sBase = (uint32_t)__cvta_generic_to_shared(g_sm);

    const __half* Ag = g_Wh + (size_t)m0 * HB;
    const __half* Bg = g_Xh + (size_t)n0 * HB;

    // ldmatrix per-lane byte offsets relative to stage base
    const int q  = lane >> 3, rr = lane & 7;
    uint32_t aOff[2], bOff[3];
    {
        const int aRow = (q & 1) * 8 + rr, aK = (q >> 1) * 8;
        const int bN   = (q >> 1) * 8 + rr, bK = (q & 1) * 8;
        #pragma unroll
        for (int mt = 0; mt < 2; mt++)
            aOff[mt] = (uint32_t)(((mb + mt * 16 + aRow) * KSH + aK) * 2);
        #pragma unroll
        for (int p = 0; p < 3; p++)
            bOff[p] = (uint32_t)((A_H + (nb + p * 16 + bN) * KSH + bK) * 2);
    }

    float c[2][6][4];
    #pragma unroll
    for (int i = 0; i < 2; i++)
        #pragma unroll
        for (int j = 0; j < 6; j++)
            #pragma unroll
            for (int qq = 0; qq < 4; qq++) c[i][j][qq] = 0.f;

    // generic chunked loader: chunk = (row, kc); rows 0..127 = A, 128..223 = B
    auto load_stage = [&](int s, int kt) {
        const int k0 = kt * KTH;
        const uint32_t stg = sBase + (uint32_t)(s * STAGE_T) * 2u;
        #pragma unroll
        for (int it = 0; it < 4; it++) {
            int ch = tid + it * 256;
            if (it < 3 || ch < CHUNKS) {
                int row = ch >> 2, kc = (ch & 3) * 8;
                const __half* src;
                uint32_t dst;
                if (row < 128) {
                    src = Ag + (size_t)row * HB + k0 + kc;
                    dst = stg + (uint32_t)(row * KSH + kc) * 2u;
                } else {
                    src = Bg + (size_t)(row - 128) * HB + k0 + kc;
                    dst = stg + (uint32_t)(A_H + (row - 128) * KSH + kc) * 2u;
                }
                cp16(dst, src);
            }
        }
        asm volatile("cp.async.commit_group;");
    };

    load_stage(0, 0);
    load_stage(1, 1);

    #pragma unroll 1
    for (int kt = 0; kt < KTILES; kt++) {
        if (kt < KTILES - 2) asm volatile("cp.async.wait_group 1;");
        else                 asm volatile("cp.async.wait_group 0;");
        __syncthreads();
        int cur = kt % NSTAGE;
        if (kt + 2 < KTILES) load_stage((kt + 2) % NSTAGE, kt + 2);

        const uint32_t stBase = sBase + (uint32_t)(cur * STAGE_T) * 2u;
        #pragma unroll
        for (int s16 = 0; s16 < 2; s16++) {
            const uint32_t khB = (uint32_t)(s16 * 16 * 2);
            uint32_t a[2][4], b[3][4];
            ldsm4(a[0], stBase + aOff[0] + khB);
            ldsm4(a[1], stBase + aOff[1] + khB);
            #pragma unroll
            for (int p = 0; p < 3; p++)
                ldsm4(b[p], stBase + bOff[p] + khB);
            #pragma unroll
            for (int mt = 0; mt < 2; mt++)
                #pragma unroll
                for (int nt = 0; nt < 6; nt++)
                    mma_f16(c[mt][nt], a[mt], &b[nt >> 1][(nt & 1) * 2]);
        }
    }

    // epilogue: +bias, relu, store Y[hm][r]
    #pragma unroll
    for (int mt = 0; mt < 2; mt++) {
        #pragma unroll
        for (int qq = 0; qq < 2; qq++) {
            int row = m0 + mb + mt * 16 + g + qq * 8;
            float bv = bias[row];
            #pragma unroll
            for (int nt = 0; nt < 6; nt++) {
                int col = n0 + nb + nt * 8 + t4 * 2;
                float2 v;
                v.x = fmaxf(c[mt][nt][qq * 2 + 0] + bv, 0.f);
                v.y = fmaxf(c[mt][nt][qq * 2 + 1] + bv, 0.f);
                *reinterpret_cast<float2*>(&g_Y[(size_t)row * RPAD + col]) = v;
            }
        }
    }
}

// ---------------- Kernel 3: assemble, 4 hm per block ----------------
// mixed[hm,1+row,1+col] = Y[hm, (49-7*(row/7)+col)*7 + row%7]
// row 0 / col 0: identity entries at multiples of 7. d = clip(rowsum,1)^-0.5.
#define GHM 4
__global__ __launch_bounds__(228) void assemble_kernel(float* __restrict__ out) {
    __shared__ float sy[GHM][RR + 1];
    __shared__ float sd[GHM][NN + 7];
    __shared__ float psum[GHM][4][NN + 1];
    __shared__ int   rbase[NN];

    const int tid = threadIdx.x;
    const int jc  = tid % 57;
    const int ty  = tid / 57;
    const int hm0 = blockIdx.x * GHM;

    #pragma unroll
    for (int gg = 0; gg < GHM; gg++) {
        const float* yr = g_Y + (size_t)(hm0 + gg) * RPAD;
        for (int r = tid; r < RR; r += 228) sy[gg][r] = yr[r];
    }
    if (tid > 0 && tid < NN) {
        int row = tid - 1, j = row / 7, n = row % 7;
        rbase[tid] = (49 - 7 * j) * 7 + n;
    }
    __syncthreads();

    {
        float acc[GHM] = {0.f, 0.f, 0.f, 0.f};
        if (jc > 0) {
            int base = rbase[jc] + ty * 14 * 7;
            #pragma unroll
            for (int cc = 0; cc < 14; cc++) {
                int idx = base + cc * 7;
                #pragma unroll
                for (int gg = 0; gg < GHM; gg++) acc[gg] += sy[gg][idx];
            }
        }
        #pragma unroll
        for (int gg = 0; gg < GHM; gg++) psum[gg][ty][jc] = acc[gg];
    }
    __syncthreads();

    if (tid < NN) {
        #pragma unroll
        for (int gg = 0; gg < GHM; gg++) {
            float s;
            if (tid == 0) s = 9.f;
            else {
                s = psum[gg][0][tid] + psum[gg][1][tid] + psum[gg][2][tid] + psum[gg][3][tid];
                if ((tid % 7) == 0) s += 1.f;
            }
            sd[gg][tid] = (s <= 1.f) ? 1.f : rsqrtf(s);
        }
    }
    __syncthreads();

    float sdj[GHM];
    float* dst[GHM];
    #pragma unroll
    for (int gg = 0; gg < GHM; gg++) {
        sdj[gg] = sd[gg][jc];
        dst[gg] = out + (size_t)(hm0 + gg) * OUTN;
    }
    const bool jc7  = (jc % 7) == 0;
    const int  gcol = (jc - 1) * 7;

    #pragma unroll
    for (int it = 0; it < 15; it++) {
        int i = ty + it * 4;
        if (i >= NN) break;
        const int off = i * NN + jc;
        if (i == 0) {
            #pragma unroll
            for (int gg = 0; gg < GHM; gg++)
                dst[gg][off] = jc7 ? sd[gg][0] * sdj[gg] : 0.f;
        } else if (jc == 0) {
            const bool i7 = (i % 7) == 0;
            #pragma unroll
            for (int gg = 0; gg < GHM; gg++)
                dst[gg][off] = i7 ? sd[gg][i] * sd[gg][0] : 0.f;
        } else {
            const int gi = rbase[i] + gcol;
            #pragma unroll
            for (int gg = 0; gg < GHM; gg++)
                dst[gg][off] = sd[gg][i] * sdj[gg] * sy[gg][gi];
        }
    }
}

// ---------------- launch ----------------
extern "C" void kernel_launch(void* const* d_in, const int* in_sizes, int n_in,
                              void* d_out, int out_size) {
    const float* mat = (const float*)d_in[0];
    const float* te  = (const float*)d_in[1];
    const float* W   = (const float*)d_in[2];
    const float* b   = (const float*)d_in[3];
    float* out = (float*)d_out;

    cudaFuncSetAttribute(gemm_kernel, cudaFuncAttributeMaxDynamicSharedMemorySize, GEMM_DYN);

    prep_kernel<<<2148, 512>>>(mat, te, (const float4*)W);
    gemm_kernel<<<dim3(8, 64), 256, GEMM_DYN>>>(b);
    assemble_kernel<<<HM / GHM, 228>>>(out);
}

// round 17
// speedup vs baseline: 1.0989x; 1.0989x over previous
#include <cuda_runtime.h>
#include <cuda_fp16.h>
#include <cstdint>

// ---------------- Problem constants ----------------
#define HB   1024          // NUM_BASIC (K)
#define HM   8192          // NUM_MIXED (GEMM M)
#define RR   735           // T*7*7 rows of X (GEMM N, logical)
#define RPAD 768           // padded N
#define NN   57            // output matrix dim
#define OUTN (NN*NN)       // 3249

// ---------------- Scratch (device globals; no allocs allowed) ----------------
__device__ __half g_Xh[RPAD * HB];             // 1.5 MB : X in fp16, rows 735..767 zero
__device__ __half g_Wh[HM * HB];               // 16.7 MB: W in fp16 (RN)
__device__ float  g_Y [(size_t)HM * RPAD];     // 25 MB  : relu(X@W^T + b), [hm][r]

// ---------------- helpers ----------------
__device__ __forceinline__ void cp16(uint32_t s, const void* g) {
    asm volatile("cp.async.cg.shared.global [%0], [%1], 16;" :: "r"(s), "l"(g));
}
__device__ __forceinline__ void mma_f16(float* c, const uint32_t* a, const uint32_t* b) {
    asm volatile(
        "mma.sync.aligned.m16n8k16.row.col.f32.f16.f16.f32 "
        "{%0,%1,%2,%3}, {%4,%5,%6,%7}, {%8,%9}, {%0,%1,%2,%3};"
        : "+f"(c[0]), "+f"(c[1]), "+f"(c[2]), "+f"(c[3])
        : "r"(a[0]), "r"(a[1]), "r"(a[2]), "r"(a[3]), "r"(b[0]), "r"(b[1]));
}
__device__ __forceinline__ void ldsm4(uint32_t* r, uint32_t addr) {
    asm volatile("ldmatrix.sync.aligned.m8n8.x4.shared.b16 {%0,%1,%2,%3}, [%4];"
        : "=r"(r[0]), "=r"(r[1]), "=r"(r[2]), "=r"(r[3]) : "r"(addr));
}

// ---------------- Kernel 1: fused prep (convert W + build X) ----------------
__global__ __launch_bounds__(512) void prep_kernel(const float* __restrict__ mat,
                                                   const float* __restrict__ te,
                                                   const float4* __restrict__ W) {
    const int b = blockIdx.x;
    if (b < 100) {
        const int p = b >> 1;
        const int h = (b & 1) * 512 + threadIdx.x;
        if (p == 49) {  // zero padding rows 735..767
            #pragma unroll
            for (int row = RR; row < RPAD; row++) g_Xh[row * HB + h] = __ushort_as_half(0);
            return;
        }
        const int m = p / 7, n = p % 7;
        const float mv = fmaxf(mat[h * 49 + n * 7 + m], 0.f);
        const int rb = m * 7 + n;
        #pragma unroll
        for (int t = 0; t < 15; t++) {
            float s = 1.f + 1.f / (1.f + __expf(-te[h * 15 + t]));
            g_Xh[(t * 49 + rb) * HB + h] = __float2half_rn(s * mv);
        }
    } else {
        const int i = (b - 100) * 512 + threadIdx.x;   // 0 .. HM*HB/8-1
        float4 v0 = W[i * 2];
        float4 v1 = W[i * 2 + 1];
        __half2 h[4];
        h[0] = __floats2half2_rn(v0.x, v0.y);
        h[1] = __floats2half2_rn(v0.z, v0.w);
        h[2] = __floats2half2_rn(v1.x, v1.y);
        h[3] = __floats2half2_rn(v1.z, v1.w);
        *reinterpret_cast<uint4*>(&g_Wh[(size_t)i * 8]) = *reinterpret_cast<uint4*>(h);
    }
}

// ---------------- Kernel 2: fp16 mma.sync GEMM, 128x96 CTA tile, 32x48 warptile ----------------
// (R13 proven config: KTH=32, 3-stage, wait_group 1)
#define NT   96            // N tile
#define KTH  32            // K halfs per smem stage
#define KSH  40            // smem row stride in halfs: 80B rows -> conflict-free LDSM/STS
#define KTILES (HB / KTH)  // 32
#define NSTAGE 3
#define A_H (128 * KSH)                     // A halfs per stage (5120)
#define B_H (NT * KSH)                      // B halfs per stage (3840)
#define STAGE_T (A_H + B_H)                 // 8960 halfs per stage
#define GEMM_DYN (NSTAGE * STAGE_T * 2)     // 53760 bytes
#define CHUNKS ((128 + NT) * 4)             // 16B chunks per stage = 896

extern __shared__ __half g_sm[];

__global__ __launch_bounds__(256, 2) void gemm_kernel(const float* __restrict__ bias) {
    const int tid  = threadIdx.x;
    const int lane = tid & 31, warp = tid >> 5;
    const int g  = lane >> 2, t4 = lane & 3;
    const int mb = (warp >> 1) * 32;   // warp grid 4(M) x 2(N)
    const int nb = (warp & 1) * 48;
    const int m0 = blockIdx.y * 128;
    const int n0 = blockIdx.x * NT;

    const uint32_t sBase = (uint32_t)__cvta_generic_to_shared(g_sm);

    const __half* Ag = g_Wh + (size_t)m0 * HB;
    const __half* Bg = g_Xh + (size_t)n0 * HB;

    // ldmatrix per-lane byte offsets relative to stage base
    const int q  = lane >> 3, rr = lane & 7;
    uint32_t aOff[2], bOff[3];
    {
        const int aRow = (q & 1) * 8 + rr, aK = (q >> 1) * 8;
        const int bN   = (q >> 1) * 8 + rr, bK = (q & 1) * 8;
        #pragma unroll
        for (int mt = 0; mt < 2; mt++)
            aOff[mt] = (uint32_t)(((mb + mt * 16 + aRow) * KSH + aK) * 2);
        #pragma unroll
        for (int p = 0; p < 3; p++)
            bOff[p] = (uint32_t)((A_H + (nb + p * 16 + bN) * KSH + bK) * 2);
    }

    float c[2][6][4];
    #pragma unroll
    for (int i = 0; i < 2; i++)
        #pragma unroll
        for (int j = 0; j < 6; j++)
            #pragma unroll
            for (int qq = 0; qq < 4; qq++) c[i][j][qq] = 0.f;

    // generic chunked loader: chunk = (row, kc); rows 0..127 = A, 128..223 = B
    auto load_stage = [&](int s, int kt) {
        const int k0 = kt * KTH;
        const uint32_t stg = sBase + (uint32_t)(s * STAGE_T) * 2u;
        #pragma unroll
        for (int it = 0; it < 4; it++) {
            int ch = tid + it * 256;
            if (it < 3 || ch < CHUNKS) {
                int row = ch >> 2, kc = (ch & 3) * 8;
                const __half* src;
                uint32_t dst;
                if (row < 128) {
                    src = Ag + (size_t)row * HB + k0 + kc;
                    dst = stg + (uint32_t)(row * KSH + kc) * 2u;
                } else {
                    src = Bg + (size_t)(row - 128) * HB + k0 + kc;
                    dst = stg + (uint32_t)(A_H + (row - 128) * KSH + kc) * 2u;
                }
                cp16(dst, src);
            }
        }
        asm volatile("cp.async.commit_group;");
    };

    load_stage(0, 0);
    load_stage(1, 1);

    #pragma unroll 1
    for (int kt = 0; kt < KTILES; kt++) {
        if (kt < KTILES - 2) asm volatile("cp.async.wait_group 1;");
        else                 asm volatile("cp.async.wait_group 0;");
        __syncthreads();
        int cur = kt % NSTAGE;
        if (kt + 2 < KTILES) load_stage((kt + 2) % NSTAGE, kt + 2);

        const uint32_t stBase = sBase + (uint32_t)(cur * STAGE_T) * 2u;
        #pragma unroll
        for (int s16 = 0; s16 < 2; s16++) {
            const uint32_t khB = (uint32_t)(s16 * 16 * 2);
            uint32_t a[2][4], b[3][4];
            ldsm4(a[0], stBase + aOff[0] + khB);
            ldsm4(a[1], stBase + aOff[1] + khB);
            #pragma unroll
            for (int p = 0; p < 3; p++)
                ldsm4(b[p], stBase + bOff[p] + khB);
            #pragma unroll
            for (int mt = 0; mt < 2; mt++)
                #pragma unroll
                for (int nt = 0; nt < 6; nt++)
                    mma_f16(c[mt][nt], a[mt], &b[nt >> 1][(nt & 1) * 2]);
        }
    }

    // epilogue: +bias, relu, store Y[hm][r]
    #pragma unroll
    for (int mt = 0; mt < 2; mt++) {
        #pragma unroll
        for (int qq = 0; qq < 2; qq++) {
            int row = m0 + mb + mt * 16 + g + qq * 8;
            float bv = bias[row];
            #pragma unroll
            for (int nt = 0; nt < 6; nt++) {
                int col = n0 + nb + nt * 8 + t4 * 2;
                float2 v;
                v.x = fmaxf(c[mt][nt][qq * 2 + 0] + bv, 0.f);
                v.y = fmaxf(c[mt][nt][qq * 2 + 1] + bv, 0.f);
                *reinterpret_cast<float2*>(&g_Y[(size_t)row * RPAD + col]) = v;
            }
        }
    }
}

// ---------------- Kernel 3: assemble, branch-free interior loop ----------------
// mixed[hm,1+row,1+col] = Y[hm, (49-7*(row/7)+col)*7 + row%7]
// row 0 / col 0: identity entries at multiples of 7. d = clip(rowsum,1)^-0.5.
__global__ __launch_bounds__(228) void assemble_kernel(float* __restrict__ out) {
    __shared__ float  sy[RR + 1];
    __shared__ float  sd[NN];
    __shared__ float  psum[4][NN + 1];
    __shared__ int    rbase[NN];
    __shared__ float2 sdrb[NN + 1];    // .x = sd[i], .y = bitcast(rbase[i]*4 bytes)

    const int tid = threadIdx.x;
    const int hm  = blockIdx.x;
    const float* yrow = g_Y + (size_t)hm * RPAD;

    for (int r = tid; r < RR; r += 228) sy[r] = yrow[r];
    if (tid > 0 && tid < NN) {
        int row = tid - 1, j = row / 7, n = row % 7;
        rbase[tid] = (49 - 7 * j) * 7 + n;
    }
    __syncthreads();

    // partial row sums (layout: jc2 = tid%57, ty2 = tid/57) — identical to R13
    {
        const int jc2 = tid % 57, ty2 = tid / 57;
        float acc = 0.f;
        if (jc2 > 0) {
            int base = rbase[jc2] + ty2 * 14 * 7;
            #pragma unroll
            for (int cc = 0; cc < 14; cc++) acc += sy[base + cc * 7];
        }
        psum[ty2][jc2] = acc;
    }
    __syncthreads();

    if (tid < NN) {
        float s;
        if (tid == 0) s = 9.f;
        else {
            s = psum[0][tid] + psum[1][tid] + psum[2][tid] + psum[3][tid];
            if ((tid % 7) == 0) s += 1.f;
        }
        float d = (s <= 1.f) ? 1.f : rsqrtf(s);
        sd[tid] = d;
        float2 pk;
        pk.x = d;
        pk.y = __int_as_float(rbase[tid] * 4);   // byte offset into sy
        sdrb[tid] = pk;
    }
    __syncthreads();

    float* dst = out + (size_t)hm * OUTN;

    // interior: i in 1..56, jc in 1..56, branch-free
    if (tid < 224) {
        const int jc = 1 + (tid % 56);     // lanes consecutive in jc -> coalesced STG
        const int ty = tid / 56;           // 0..3
        const float sdjc = sd[jc];
        const char* syb  = (const char*)sy + (jc - 1) * 28;   // + (jc-1)*7 floats
        float* op = dst + (1 + ty) * NN + jc;
        #pragma unroll
        for (int it = 0; it < 14; it++) {
            const int i = 1 + ty + it * 4;
            float2 sr = sdrb[i];                               // LDS.64, immediate offset
            float  f  = *(const float*)(syb + __float_as_int(sr.y));
            op[it * 4 * NN] = sr.x * sdjc * f;                 // immediate offsets
        }
    }

    // border: row 0 and column 0
    if (tid < NN) {
        const bool t7 = (tid % 7) == 0;
        const float v = t7 ? sd[0] * sd[tid] : 0.f;
        dst[tid]      = v;                 // row 0, col tid
        if (tid > 0) dst[tid * NN] = v;    // col 0, row tid (sd[tid]*sd[0] == v)
    }
}

// ---------------- launch ----------------
extern "C" void kernel_launch(void* const* d_in, const int* in_sizes, int n_in,
                              void* d_out, int out_size) {
    const float* mat = (const float*)d_in[0];
    const float* te  = (const float*)d_in[1];
    const float* W   = (const float*)d_in[2];
    const float* b   = (const float*)d_in[3];
    float* out = (float*)d_out;

    cudaFuncSetAttribute(gemm_kernel, cudaFuncAttributeMaxDynamicSharedMemorySize, GEMM_DYN);

    prep_kernel<<<2148, 512>>>(mat, te, (const float4*)W);
    gemm_kernel<<<dim3(8, 64), 256, GEMM_DYN>>>(b);
    assemble_kernel<<<HM, 228>>>(out);
}